// round 8
// baseline (speedup 1.0000x reference)
#include <cuda_runtime.h>
#include <cuda_bf16.h>
#include <math.h>
#include <stdint.h>

#define BATCH   4
#define LSEQ    2048
#define DMODEL  512
#define DINNER  1024
#define DSTATE  16
#define DTRANK  32
#define NROWS   (BATCH * LSEQ)         // 8192
#define XPROJN  (DTRANK + 2 * DSTATE)  // 64
#define NC      64                     // scan chunks
#define LC      32                     // steps per chunk

// ---------------- scratch (static device globals: no allocs allowed) --------
__device__ float g_xz  [NROWS * 2 * DINNER];    // [u_raw | z]
__device__ float g_u   [NROWS * DINNER];        // silu(conv(u)+b)
__device__ float g_xdbl[NROWS * XPROJN];        // [dt_r | B | C]
__device__ float g_dt  [NROWS * DINNER];        // softplus(dt)
__device__ float g_yo  [NROWS * DMODEL];        // y @ W_out
__device__ float g_S    [NC * BATCH * DINNER * DSTATE];  // chunk end states
__device__ float g_Hini [NC * BATCH * DINNER * DSTATE];  // chunk init states
__device__ float g_dts  [NC * BATCH * DINNER];           // chunk dt sums

// bf16 split operands for tensor-core GEMMs
__device__ __nv_bfloat16 gA1h[NROWS * DMODEL],  gA1l[NROWS * DMODEL];   // LN1 out
__device__ __nv_bfloat16 gA2h[NROWS * DINNER],  gA2l[NROWS * DINNER];   // scan out
__device__ __nv_bfloat16 gW1h[2 * DINNER * DMODEL], gW1l[2 * DINNER * DMODEL]; // W_in^T  [2048][512]
__device__ __nv_bfloat16 gW2h[DMODEL * DINNER],     gW2l[DMODEL * DINNER];     // W_out^T [512][1024]

// ---------------- helpers ----------------------------------------------------
__device__ __forceinline__ uint32_t smem_u32(const void* p) {
    uint32_t a;
    asm("{ .reg .u64 t; cvta.to.shared.u64 t, %1; cvt.u32.u64 %0, t; }" : "=r"(a) : "l"(p));
    return a;
}
__device__ __forceinline__ void split_store(float v, __nv_bfloat16* h, __nv_bfloat16* l, size_t i) {
    __nv_bfloat16 hb = __float2bfloat16(v);
    h[i] = hb;
    l[i] = __float2bfloat16(v - __bfloat162float(hb));
}
__device__ __forceinline__ void ldsm4(uint32_t* r, uint32_t addr) {
    asm volatile("ldmatrix.sync.aligned.m8n8.x4.shared.b16 {%0,%1,%2,%3}, [%4];"
                 : "=r"(r[0]), "=r"(r[1]), "=r"(r[2]), "=r"(r[3]) : "r"(addr));
}
__device__ __forceinline__ void mma16816(float* c, const uint32_t* a, uint32_t b0, uint32_t b1) {
    asm volatile(
        "mma.sync.aligned.m16n8k16.row.col.f32.bf16.bf16.f32 "
        "{%0,%1,%2,%3}, {%4,%5,%6,%7}, {%8,%9}, {%0,%1,%2,%3};"
        : "+f"(c[0]), "+f"(c[1]), "+f"(c[2]), "+f"(c[3])
        : "r"(a[0]), "r"(a[1]), "r"(a[2]), "r"(a[3]), "r"(b0), "r"(b1));
}
__device__ __forceinline__ void cpasync16(uint32_t dst, const void* src) {
    asm volatile("cp.async.cg.shared.global [%0], [%1], 16;" :: "r"(dst), "l"(src));
}
__device__ __forceinline__ void cp_commit() { asm volatile("cp.async.commit_group;" ::: "memory"); }
__device__ __forceinline__ void cp_wait1()  { asm volatile("cp.async.wait_group 1;" ::: "memory"); }
__device__ __forceinline__ void cp_wait0()  { asm volatile("cp.async.wait_group 0;" ::: "memory"); }
// packed fp32x2 (xproj)
__device__ __forceinline__ unsigned long long pack2(float a) {
    unsigned long long r;
    asm("mov.b64 %0, {%1, %1};" : "=l"(r) : "f"(a));
    return r;
}
__device__ __forceinline__ void fma2(unsigned long long& d,
                                     unsigned long long a,
                                     unsigned long long b) {
    asm("fma.rn.f32x2 %0, %1, %2, %0;" : "+l"(d) : "l"(a), "l"(b));
}

// ---------------- layernorm ---------------------------------------------------
template<int MODE>
__global__ void ln_kernel(const float* __restrict__ x,
                          const float* __restrict__ w,
                          const float* __restrict__ b,
                          float* __restrict__ outp) {
    __shared__ float sbuf[4];
    int row = blockIdx.x;
    int tid = threadIdx.x;
    float4 v = reinterpret_cast<const float4*>(x + (size_t)row * DMODEL)[tid];
    if (MODE == 1) {
        float4 r = reinterpret_cast<const float4*>(g_yo + (size_t)row * DMODEL)[tid];
        v.x += r.x; v.y += r.y; v.z += r.z; v.w += r.w;
    }
    float s = v.x + v.y + v.z + v.w;
    #pragma unroll
    for (int o = 16; o > 0; o >>= 1) s += __shfl_xor_sync(0xffffffffu, s, o);
    if ((tid & 31) == 0) sbuf[tid >> 5] = s;
    __syncthreads();
    float mean = (sbuf[0] + sbuf[1] + sbuf[2] + sbuf[3]) * (1.0f / DMODEL);
    __syncthreads();
    float dx = v.x - mean, dy = v.y - mean, dz = v.z - mean, dw = v.w - mean;
    float sq = dx * dx + dy * dy + dz * dz + dw * dw;
    #pragma unroll
    for (int o = 16; o > 0; o >>= 1) sq += __shfl_xor_sync(0xffffffffu, sq, o);
    if ((tid & 31) == 0) sbuf[tid >> 5] = sq;
    __syncthreads();
    float var = (sbuf[0] + sbuf[1] + sbuf[2] + sbuf[3]) * (1.0f / DMODEL);
    float inv = rsqrtf(var + 1e-5f);
    float4 wv = reinterpret_cast<const float4*>(w)[tid];
    float4 bv = reinterpret_cast<const float4*>(b)[tid];
    float o0 = dx * inv * wv.x + bv.x;
    float o1 = dy * inv * wv.y + bv.y;
    float o2 = dz * inv * wv.z + bv.z;
    float o3 = dw * inv * wv.w + bv.w;
    if (MODE == 0) {
        size_t base = (size_t)row * DMODEL + tid * 4;
        split_store(o0, gA1h, gA1l, base + 0);
        split_store(o1, gA1h, gA1l, base + 1);
        split_store(o2, gA1h, gA1l, base + 2);
        split_store(o3, gA1h, gA1l, base + 3);
    } else {
        float4 o4; o4.x = o0; o4.y = o1; o4.z = o2; o4.w = o3;
        reinterpret_cast<float4*>(outp + (size_t)row * DMODEL)[tid] = o4;
    }
}

// ---------------- transpose + bf16 split for both weights (merged) ----------
__global__ void tsplit_all(const float* __restrict__ W_in,
                           const float* __restrict__ W_out) {
    int blk = blockIdx.x;
    int R, Cc, bx, by;
    const float* src;
    __nv_bfloat16 *dh, *dl;
    if (blk < 1024) {               // W_in [512][2048] -> [2048][512]
        R = DMODEL; Cc = 2 * DINNER; src = W_in; dh = gW1h; dl = gW1l;
        bx = blk & 63; by = blk >> 6;
    } else {                        // W_out [1024][512] -> [512][1024]
        int b2 = blk - 1024;
        R = DINNER; Cc = DMODEL; src = W_out; dh = gW2h; dl = gW2l;
        bx = b2 & 15; by = b2 >> 4;
    }
    __shared__ float t[32][33];
    int tx = threadIdx.x & 31, tq = threadIdx.x >> 5;
    #pragma unroll
    for (int j = 0; j < 32; j += 8)
        t[tq + j][tx] = src[(size_t)(by * 32 + tq + j) * Cc + bx * 32 + tx];
    __syncthreads();
    #pragma unroll
    for (int j = 0; j < 32; j += 8) {
        float v = t[tx][tq + j];
        size_t di = (size_t)(bx * 32 + tq + j) * R + by * 32 + tx;
        split_store(v, dh, dl, di);
    }
}

// ---------------- HMMA GEMM, BK=32, 2-stage cp.async, 2 CTAs/SM -------------
// MODE 0: g_xz[8192,2048] = A1 @ W1t^T   (K=512)
// MODE 1: g_yo[8192, 512] = A2 @ W2t^T   (K=1024)
// smem layout: per stage 4 operand tiles (Ah,Al,Bh,Bl), each 128 rows x 32
// bf16 cols stored with 80-byte row stride (16B aligned, bank-safe).
#define OPBYTES     10240            // 128 * 80
#define STAGE_BYTES 40960            // 4 * OPBYTES
#define GEMM_SMEM   (2 * STAGE_BYTES)
template<int MODE>
__global__ __launch_bounds__(256, 2)
void gemm_hmma() {
    constexpr int N = (MODE == 0) ? 2 * DINNER : DMODEL;
    constexpr int K = (MODE == 0) ? DMODEL : DINNER;
    constexpr int KT = K / 32;
    const __nv_bfloat16* Ah_g = (MODE == 0) ? gA1h : gA2h;
    const __nv_bfloat16* Al_g = (MODE == 0) ? gA1l : gA2l;
    const __nv_bfloat16* Bh_g = (MODE == 0) ? gW1h : gW2h;
    const __nv_bfloat16* Bl_g = (MODE == 0) ? gW1l : gW2l;
    float* C = (MODE == 0) ? g_xz : g_yo;

    extern __shared__ __align__(256) char smem[];
    uint32_t sb = smem_u32(smem);
    int tid = threadIdx.x, lane = tid & 31, wid = tid >> 5;
    int bx = blockIdx.x, by = blockIdx.y;
    int m0 = (wid >> 1) * 32;
    int n0 = (wid & 1) * 64;

    float c[2][8][4];
    #pragma unroll
    for (int i = 0; i < 2; i++)
        #pragma unroll
        for (int j = 0; j < 8; j++)
            #pragma unroll
            for (int q = 0; q < 4; q++) c[i][j][q] = 0.0f;

    auto issue = [&](int stage, int kt) {
        uint32_t s0 = sb + stage * STAGE_BYTES;
        #pragma unroll
        for (int op = 0; op < 4; op++) {
            const __nv_bfloat16* base =
                (op == 0) ? Ah_g : (op == 1) ? Al_g : (op == 2) ? Bh_g : Bl_g;
            int rowoff = (op < 2) ? by * 128 : bx * 128;
            #pragma unroll
            for (int j = 0; j < 2; j++) {
                int idx2 = tid + j * 256;          // 0..511
                int row = idx2 >> 2, c16 = idx2 & 3;
                cpasync16(s0 + op * OPBYTES + row * 80 + c16 * 16,
                          base + (size_t)(rowoff + row) * K + kt * 32 + c16 * 8);
            }
        }
        cp_commit();
    };

    issue(0, 0);
    for (int kt = 0; kt < KT; kt++) {
        int cur = kt & 1;
        if (kt + 1 < KT) { issue(cur ^ 1, kt + 1); cp_wait1(); }
        else             { cp_wait0(); }
        __syncthreads();
        uint32_t bb = sb + cur * STAGE_BYTES;
        #pragma unroll
        for (int ks = 0; ks < 2; ks++) {
            int r = lane & 15;
            uint32_t coff = (uint32_t)(ks * 2 + (lane >> 4)) * 16;
            uint32_t ah[2][4], al[2][4];
            #pragma unroll
            for (int mi = 0; mi < 2; mi++) {
                uint32_t a0 = bb + (uint32_t)(m0 + mi * 16 + r) * 80 + coff;
                ldsm4(ah[mi], a0);
                ldsm4(al[mi], a0 + OPBYTES);
            }
            #pragma unroll
            for (int nq = 0; nq < 4; nq++) {
                uint32_t b0a = bb + 2 * OPBYTES + (uint32_t)(n0 + nq * 16 + r) * 80 + coff;
                uint32_t bh[4], bl[4];
                ldsm4(bh, b0a);
                ldsm4(bl, b0a + OPBYTES);
                #pragma unroll
                for (int mi = 0; mi < 2; mi++) {
                    #pragma unroll
                    for (int sub = 0; sub < 2; sub++) {
                        float* cc = c[mi][nq * 2 + sub];
                        uint32_t h0 = sub ? bh[1] : bh[0];
                        uint32_t h1 = sub ? bh[3] : bh[2];
                        mma16816(cc, ah[mi], h0, h1);
                        mma16816(cc, al[mi], h0, h1);
                        uint32_t l0 = sub ? bl[1] : bl[0];
                        uint32_t l1 = sub ? bl[3] : bl[2];
                        mma16816(cc, ah[mi], l0, l1);
                    }
                }
            }
        }
        __syncthreads();
    }

    int gid = lane >> 2, tig = lane & 3;
    #pragma unroll
    for (int mi = 0; mi < 2; mi++) {
        #pragma unroll
        for (int nb = 0; nb < 8; nb++) {
            float* p = C + (size_t)(by * 128 + m0 + mi * 16 + gid) * N
                         + bx * 128 + n0 + nb * 8 + 2 * tig;
            float2 v0; v0.x = c[mi][nb][0]; v0.y = c[mi][nb][1];
            float2 v1; v1.x = c[mi][nb][2]; v1.y = c[mi][nb][3];
            *reinterpret_cast<float2*>(p) = v0;
            *reinterpret_cast<float2*>(p + (size_t)8 * N) = v1;
        }
    }
}

// ---------------- causal depthwise conv (width 4) + bias + silu -------------
__global__ void conv_silu_kernel(const float* __restrict__ conv_w,
                                 const float* __restrict__ conv_b) {
    int idx = blockIdx.x * blockDim.x + threadIdx.x;
    int e = idx & (DINNER - 1);
    int row = idx >> 10;
    int l = row & (LSEQ - 1);
    int base = row * 2 * DINNER + e;
    float w0 = conv_w[e * 4 + 0], w1 = conv_w[e * 4 + 1];
    float w2 = conv_w[e * 4 + 2], w3 = conv_w[e * 4 + 3];
    float v = conv_b[e];
    if (l >= 3) v += g_xz[base - 3 * 2 * DINNER] * w0;
    if (l >= 2) v += g_xz[base - 2 * 2 * DINNER] * w1;
    if (l >= 1) v += g_xz[base - 1 * 2 * DINNER] * w2;
    v += g_xz[base] * w3;
    g_u[idx] = v / (1.0f + __expf(-v));
}

// ---------------- x_dbl = u @ W_xproj (8192 x 1024 x 64) --------------------
// 16-row tiles, 256 threads (16 rows x 16 colgroups), FFMA2. grid = 512.
__global__ __launch_bounds__(256)
void xproj_kernel(const float* __restrict__ W) {
    __shared__ float As[32][17];   // [k][row]
    __shared__ float Bs[32][64];
    int tid = threadIdx.x;
    int by = blockIdx.x;
    const float* Ab = g_u + (size_t)(by * 16) * DINNER;
    int ty = tid >> 4, tx = tid & 15;

    unsigned long long acc2[2];
    acc2[0] = 0ull; acc2[1] = 0ull;

    for (int k0 = 0; k0 < DINNER; k0 += 32) {
        if (tid < 128) {
            int row = tid >> 3, c4 = (tid & 7) * 4;
            float4 av = *reinterpret_cast<const float4*>(Ab + (size_t)row * DINNER + k0 + c4);
            As[c4 + 0][row] = av.x;
            As[c4 + 1][row] = av.y;
            As[c4 + 2][row] = av.z;
            As[c4 + 3][row] = av.w;
        } else {
            int t2 = tid - 128;
            #pragma unroll
            for (int j = 0; j < 4; j++) {
                int idx = t2 + j * 128;
                int brow = idx >> 4, bcol = (idx & 15) * 4;
                *reinterpret_cast<float4*>(&Bs[brow][bcol]) =
                    *reinterpret_cast<const float4*>(W + (size_t)(k0 + brow) * XPROJN + bcol);
            }
        }
        __syncthreads();
        #pragma unroll 8
        for (int k = 0; k < 32; k++) {
            unsigned long long a2 = pack2(As[k][ty]);
            ulonglong2 rb = *reinterpret_cast<const ulonglong2*>(&Bs[k][tx * 4]);
            fma2(acc2[0], a2, rb.x);
            fma2(acc2[1], a2, rb.y);
        }
        __syncthreads();
    }
    ulonglong2 v; v.x = acc2[0]; v.y = acc2[1];
    *reinterpret_cast<ulonglong2*>(g_xdbl + (size_t)(by * 16 + ty) * XPROJN + tx * 4) = v;
}

// ---------------- dt = softplus(dt_r @ W_dt + b_dt) -------------------------
__global__ __launch_bounds__(256)
void dtproj_kernel(const float* __restrict__ W_dt, const float* __restrict__ b_dt) {
    __shared__ float dtr_s[8][DTRANK];
    int tid = threadIdx.x;
    int r0 = blockIdx.x * 8;
    {
        int r = tid >> 5, k = tid & 31;
        dtr_s[r][k] = g_xdbl[(size_t)(r0 + r) * XPROJN + k];
    }
    __syncthreads();
    float acc[8][4];
    #pragma unroll
    for (int i = 0; i < 8; i++)
        #pragma unroll
        for (int j = 0; j < 4; j++) acc[i][j] = 0.0f;
    #pragma unroll 4
    for (int k = 0; k < DTRANK; k++) {
        float wv[4];
        #pragma unroll
        for (int j = 0; j < 4; j++) wv[j] = W_dt[(size_t)k * DINNER + tid + j * 256];
        #pragma unroll
        for (int i = 0; i < 8; i++) {
            float a = dtr_s[i][k];
            #pragma unroll
            for (int j = 0; j < 4; j++) acc[i][j] = fmaf(a, wv[j], acc[i][j]);
        }
    }
    #pragma unroll
    for (int j = 0; j < 4; j++) {
        int col = tid + j * 256;
        float bb = b_dt[col];
        #pragma unroll
        for (int i = 0; i < 8; i++) {
            float v = acc[i][j] + bb;
            float sp = (v > 20.0f) ? v : log1pf(__expf(v));
            g_dt[(size_t)(r0 + i) * DINNER + col] = sp;
        }
    }
}

// ---------------- chunked selective scan ------------------------------------
// scan1: per-chunk local scan from h=0 -> S_c, sum(dt).  grid (8, BATCH, NC)
__global__ __launch_bounds__(128)
void scan1_kernel(const float* __restrict__ A_log) {
    __shared__ float dt_s[LC][128];
    __shared__ float u_s [LC][128];
    __shared__ float B_s [LC][DSTATE];
    int tid = threadIdx.x;
    int e = blockIdx.x * 128 + tid;
    int b = blockIdx.y, cch = blockIdx.z;
    int l0 = cch * LC;

    float Ar[DSTATE];
    #pragma unroll
    for (int n = 0; n < DSTATE; n++) Ar[n] = -__expf(A_log[e * DSTATE + n]);

    #pragma unroll
    for (int t = 0; t < LC; t++) {
        size_t row = (size_t)(b * LSEQ + l0 + t);
        dt_s[t][tid] = g_dt[row * DINNER + e];
        u_s [t][tid] = g_u [row * DINNER + e];
    }
    for (int idx = tid; idx < LC * DSTATE; idx += 128) {
        int t = idx >> 4, n = idx & 15;
        size_t row = (size_t)(b * LSEQ + l0 + t);
        B_s[t][n] = g_xdbl[row * XPROJN + DTRANK + n];
    }
    __syncthreads();

    float h[DSTATE];
    #pragma unroll
    for (int n = 0; n < DSTATE; n++) h[n] = 0.0f;
    float dts = 0.0f;
    #pragma unroll 4
    for (int t = 0; t < LC; t++) {
        float dt = dt_s[t][tid];
        dts += dt;
        float du = dt * u_s[t][tid];
        #pragma unroll
        for (int n = 0; n < DSTATE; n++) {
            float dA = __expf(dt * Ar[n]);
            h[n] = fmaf(dA, h[n], du * B_s[t][n]);
        }
    }
    size_t sbase = ((size_t)(cch * BATCH + b) * DINNER + e);
    float* Sp = g_S + sbase * DSTATE;
    #pragma unroll
    for (int n = 0; n < DSTATE; n += 4) {
        float4 v; v.x = h[n]; v.y = h[n + 1]; v.z = h[n + 2]; v.w = h[n + 3];
        *reinterpret_cast<float4*>(Sp + n) = v;
    }
    g_dts[sbase] = dts;
}

// scan2: chunk stitch, parallel over (channel, state). grid (64, BATCH), 256 thr
__global__ __launch_bounds__(256)
void scan2_kernel(const float* __restrict__ A_log) {
    int tid = threadIdx.x;
    int el = tid >> 4, n = tid & 15;
    int e = blockIdx.x * 16 + el;
    int b = blockIdx.y;
    float Ar = -__expf(A_log[e * DSTATE + n]);
    float h = 0.0f;
    #pragma unroll 4
    for (int cch = 0; cch < NC; cch++) {
        size_t sbase = ((size_t)(cch * BATCH + b) * DINNER + e);
        float dts = g_dts[sbase];
        g_Hini[sbase * DSTATE + n] = h;
        h = fmaf(__expf(Ar * dts), h, g_S[sbase * DSTATE + n]);
    }
}

// scan3: replay chunk with true init state, emit gated output. grid (8,BATCH,NC)
__global__ __launch_bounds__(128)
void scan3_kernel(const float* __restrict__ A_log, const float* __restrict__ D_param) {
    __shared__ float dt_s[LC][128];
    __shared__ float u_s [LC][128];
    __shared__ float B_s [LC][DSTATE];
    __shared__ float C_s [LC][DSTATE];
    int tid = threadIdx.x;
    int e = blockIdx.x * 128 + tid;
    int b = blockIdx.y, cch = blockIdx.z;
    int l0 = cch * LC;

    float Ar[DSTATE];
    #pragma unroll
    for (int n = 0; n < DSTATE; n++) Ar[n] = -__expf(A_log[e * DSTATE + n]);
    float Dp = D_param[e];

    #pragma unroll
    for (int t = 0; t < LC; t++) {
        size_t row = (size_t)(b * LSEQ + l0 + t);
        dt_s[t][tid] = g_dt[row * DINNER + e];
        u_s [t][tid] = g_u [row * DINNER + e];
    }
    for (int idx = tid; idx < LC * DSTATE; idx += 128) {
        int t = idx >> 4, n = idx & 15;
        size_t row = (size_t)(b * LSEQ + l0 + t);
        B_s[t][n] = g_xdbl[row * XPROJN + DTRANK + n];
        C_s[t][n] = g_xdbl[row * XPROJN + DTRANK + DSTATE + n];
    }
    __syncthreads();

    float h[DSTATE];
    {
        const float* Hp = g_Hini + ((size_t)(cch * BATCH + b) * DINNER + e) * DSTATE;
        #pragma unroll
        for (int n = 0; n < DSTATE; n += 4) {
            float4 v = *reinterpret_cast<const float4*>(Hp + n);
            h[n] = v.x; h[n + 1] = v.y; h[n + 2] = v.z; h[n + 3] = v.w;
        }
    }

    #pragma unroll 4
    for (int t = 0; t < LC; t++) {
        float dt = dt_s[t][tid];
        float u  = u_s [t][tid];
        float du = dt * u;
        float y = 0.0f;
        #pragma unroll
        for (int n = 0; n < DSTATE; n++) {
            float dA = __expf(dt * Ar[n]);
            h[n] = fmaf(dA, h[n], du * B_s[t][n]);
            y = fmaf(h[n], C_s[t][n], y);
        }
        size_t row = (size_t)(b * LSEQ + l0 + t);
        float z = g_xz[row * 2 * DINNER + DINNER + e];
        float g = z / (1.0f + __expf(-z));
        split_store((y + u * Dp) * g, gA2h, gA2l, row * DINNER + e);
    }
}

// ---------------- launch ----------------------------------------------------
extern "C" void kernel_launch(void* const* d_in, const int* in_sizes, int n_in,
                              void* d_out, int out_size) {
    const float* x      = (const float*)d_in[0];
    const float* ln1_w  = (const float*)d_in[1];
    const float* ln1_b  = (const float*)d_in[2];
    const float* ln2_w  = (const float*)d_in[3];
    const float* ln2_b  = (const float*)d_in[4];
    const float* W_in   = (const float*)d_in[5];
    const float* conv_w = (const float*)d_in[6];
    const float* conv_b = (const float*)d_in[7];
    const float* W_xprj = (const float*)d_in[8];
    const float* W_dt   = (const float*)d_in[9];
    const float* b_dt   = (const float*)d_in[10];
    const float* A_log  = (const float*)d_in[11];
    const float* D_prm  = (const float*)d_in[12];
    const float* W_out  = (const float*)d_in[13];
    float* out = (float*)d_out;

    static int attr_done = 0;
    if (!attr_done) {
        cudaFuncSetAttribute(gemm_hmma<0>, cudaFuncAttributeMaxDynamicSharedMemorySize, GEMM_SMEM);
        cudaFuncSetAttribute(gemm_hmma<1>, cudaFuncAttributeMaxDynamicSharedMemorySize, GEMM_SMEM);
        attr_done = 1;
    }

    // 0) weight transposes + splits (merged)
    tsplit_all<<<1536, 256>>>(W_in, W_out);
    // 1) LN1 -> split bf16 A1
    ln_kernel<0><<<NROWS, 128>>>(x, ln1_w, ln1_b, nullptr);
    // 2) g_xz = A1 @ W_in (HMMA, 2 CTA/SM)
    gemm_hmma<0><<<dim3(2 * DINNER / 128, NROWS / 128), 256, GEMM_SMEM>>>();
    // 3) depthwise causal conv + silu -> g_u
    conv_silu_kernel<<<NROWS * DINNER / 256, 256>>>(conv_w, conv_b);
    // 4) g_xdbl = g_u @ W_xproj
    xproj_kernel<<<NROWS / 16, 256>>>(W_xprj);
    // 5) g_dt = softplus(dt_r @ W_dt + b_dt)
    dtproj_kernel<<<NROWS / 8, 256>>>(W_dt, b_dt);
    // 6) chunked selective scan -> split bf16 A2
    scan1_kernel<<<dim3(DINNER / 128, BATCH, NC), 128>>>(A_log);
    scan2_kernel<<<dim3(DINNER / 16, BATCH), 256>>>(A_log);
    scan3_kernel<<<dim3(DINNER / 128, BATCH, NC), 128>>>(A_log, D_prm);
    // 7) g_yo = A2 @ W_out (HMMA, 2 CTA/SM)
    gemm_hmma<1><<<dim3(DMODEL / 128, NROWS / 128), 256, GEMM_SMEM>>>();
    // 8) out = LN2(x + g_yo)
    ln_kernel<1><<<NROWS, 128>>>(x, ln2_w, ln2_b, out);
}

// round 10
// speedup vs baseline: 1.0471x; 1.0471x over previous
#include <cuda_runtime.h>
#include <cuda_bf16.h>
#include <math.h>
#include <stdint.h>

#define BATCH   4
#define LSEQ    2048
#define DMODEL  512
#define DINNER  1024
#define DSTATE  16
#define DTRANK  32
#define NROWS   (BATCH * LSEQ)         // 8192
#define XPROJN  (DTRANK + 2 * DSTATE)  // 64
#define NC      64                     // scan chunks
#define LC      32                     // steps per chunk

// ---------------- scratch (static device globals: no allocs allowed) --------
__device__ float g_xz  [NROWS * 2 * DINNER];    // [u_raw | z]
__device__ float g_u   [NROWS * DINNER];        // silu(conv(u)+b)
__device__ float g_xdbl[NROWS * XPROJN];        // [dt_r | B | C]
__device__ float g_dt  [NROWS * DINNER];        // softplus(dt)
__device__ float g_yo  [NROWS * DMODEL];        // y @ W_out
__device__ float g_S    [NC * BATCH * DINNER * DSTATE];  // chunk end states
__device__ float g_Hini [NC * BATCH * DINNER * DSTATE];  // chunk init states
__device__ float g_dts  [NC * BATCH * DINNER];           // chunk dt sums

// bf16 split operands for tensor-core GEMMs
__device__ __nv_bfloat16 gA1h[NROWS * DMODEL],  gA1l[NROWS * DMODEL];   // LN1 out
__device__ __nv_bfloat16 gA2h[NROWS * DINNER],  gA2l[NROWS * DINNER];   // scan out
__device__ __nv_bfloat16 gW1h[2 * DINNER * DMODEL], gW1l[2 * DINNER * DMODEL]; // W_in^T  [2048][512]
__device__ __nv_bfloat16 gW2h[DMODEL * DINNER],     gW2l[DMODEL * DINNER];     // W_out^T [512][1024]

// ---------------- helpers ----------------------------------------------------
__device__ __forceinline__ uint32_t smem_u32(const void* p) {
    uint32_t a;
    asm("{ .reg .u64 t; cvta.to.shared.u64 t, %1; cvt.u32.u64 %0, t; }" : "=r"(a) : "l"(p));
    return a;
}
__device__ __forceinline__ void split_store(float v, __nv_bfloat16* h, __nv_bfloat16* l, size_t i) {
    __nv_bfloat16 hb = __float2bfloat16(v);
    h[i] = hb;
    l[i] = __float2bfloat16(v - __bfloat162float(hb));
}
__device__ __forceinline__ void ldsm4(uint32_t* r, uint32_t addr) {
    asm volatile("ldmatrix.sync.aligned.m8n8.x4.shared.b16 {%0,%1,%2,%3}, [%4];"
                 : "=r"(r[0]), "=r"(r[1]), "=r"(r[2]), "=r"(r[3]) : "r"(addr));
}
__device__ __forceinline__ void mma16816(float* c, const uint32_t* a, uint32_t b0, uint32_t b1) {
    asm volatile(
        "mma.sync.aligned.m16n8k16.row.col.f32.bf16.bf16.f32 "
        "{%0,%1,%2,%3}, {%4,%5,%6,%7}, {%8,%9}, {%0,%1,%2,%3};"
        : "+f"(c[0]), "+f"(c[1]), "+f"(c[2]), "+f"(c[3])
        : "r"(a[0]), "r"(a[1]), "r"(a[2]), "r"(a[3]), "r"(b0), "r"(b1));
}
__device__ __forceinline__ void cpasync16(uint32_t dst, const void* src) {
    asm volatile("cp.async.cg.shared.global [%0], [%1], 16;" :: "r"(dst), "l"(src));
}
__device__ __forceinline__ void cp_commit() { asm volatile("cp.async.commit_group;" ::: "memory"); }
__device__ __forceinline__ void cp_wait2()  { asm volatile("cp.async.wait_group 2;" ::: "memory"); }
__device__ __forceinline__ void cp_wait1()  { asm volatile("cp.async.wait_group 1;" ::: "memory"); }
__device__ __forceinline__ void cp_wait0()  { asm volatile("cp.async.wait_group 0;" ::: "memory"); }
// packed fp32x2 (xproj)
__device__ __forceinline__ unsigned long long pack2(float a) {
    unsigned long long r;
    asm("mov.b64 %0, {%1, %1};" : "=l"(r) : "f"(a));
    return r;
}
__device__ __forceinline__ void fma2(unsigned long long& d,
                                     unsigned long long a,
                                     unsigned long long b) {
    asm("fma.rn.f32x2 %0, %1, %2, %0;" : "+l"(d) : "l"(a), "l"(b));
}

// ---------------- layernorm ---------------------------------------------------
template<int MODE>
__global__ void ln_kernel(const float* __restrict__ x,
                          const float* __restrict__ w,
                          const float* __restrict__ b,
                          float* __restrict__ outp) {
    __shared__ float sbuf[4];
    int row = blockIdx.x;
    int tid = threadIdx.x;
    float4 v = reinterpret_cast<const float4*>(x + (size_t)row * DMODEL)[tid];
    if (MODE == 1) {
        float4 r = reinterpret_cast<const float4*>(g_yo + (size_t)row * DMODEL)[tid];
        v.x += r.x; v.y += r.y; v.z += r.z; v.w += r.w;
    }
    float s = v.x + v.y + v.z + v.w;
    #pragma unroll
    for (int o = 16; o > 0; o >>= 1) s += __shfl_xor_sync(0xffffffffu, s, o);
    if ((tid & 31) == 0) sbuf[tid >> 5] = s;
    __syncthreads();
    float mean = (sbuf[0] + sbuf[1] + sbuf[2] + sbuf[3]) * (1.0f / DMODEL);
    __syncthreads();
    float dx = v.x - mean, dy = v.y - mean, dz = v.z - mean, dw = v.w - mean;
    float sq = dx * dx + dy * dy + dz * dz + dw * dw;
    #pragma unroll
    for (int o = 16; o > 0; o >>= 1) sq += __shfl_xor_sync(0xffffffffu, sq, o);
    if ((tid & 31) == 0) sbuf[tid >> 5] = sq;
    __syncthreads();
    float var = (sbuf[0] + sbuf[1] + sbuf[2] + sbuf[3]) * (1.0f / DMODEL);
    float inv = rsqrtf(var + 1e-5f);
    float4 wv = reinterpret_cast<const float4*>(w)[tid];
    float4 bv = reinterpret_cast<const float4*>(b)[tid];
    float o0 = dx * inv * wv.x + bv.x;
    float o1 = dy * inv * wv.y + bv.y;
    float o2 = dz * inv * wv.z + bv.z;
    float o3 = dw * inv * wv.w + bv.w;
    if (MODE == 0) {
        size_t base = (size_t)row * DMODEL + tid * 4;
        split_store(o0, gA1h, gA1l, base + 0);
        split_store(o1, gA1h, gA1l, base + 1);
        split_store(o2, gA1h, gA1l, base + 2);
        split_store(o3, gA1h, gA1l, base + 3);
    } else {
        float4 o4; o4.x = o0; o4.y = o1; o4.z = o2; o4.w = o3;
        reinterpret_cast<float4*>(outp + (size_t)row * DMODEL)[tid] = o4;
    }
}

// ---------------- transpose + bf16 split for both weights (merged) ----------
__global__ void tsplit_all(const float* __restrict__ W_in,
                           const float* __restrict__ W_out) {
    int blk = blockIdx.x;
    int R, Cc, bx, by;
    const float* src;
    __nv_bfloat16 *dh, *dl;
    if (blk < 1024) {               // W_in [512][2048] -> [2048][512]
        R = DMODEL; Cc = 2 * DINNER; src = W_in; dh = gW1h; dl = gW1l;
        bx = blk & 63; by = blk >> 6;
    } else {                        // W_out [1024][512] -> [512][1024]
        int b2 = blk - 1024;
        R = DINNER; Cc = DMODEL; src = W_out; dh = gW2h; dl = gW2l;
        bx = b2 & 15; by = b2 >> 4;
    }
    __shared__ float t[32][33];
    int tx = threadIdx.x & 31, tq = threadIdx.x >> 5;
    #pragma unroll
    for (int j = 0; j < 32; j += 8)
        t[tq + j][tx] = src[(size_t)(by * 32 + tq + j) * Cc + bx * 32 + tx];
    __syncthreads();
    #pragma unroll
    for (int j = 0; j < 32; j += 8) {
        float v = t[tx][tq + j];
        size_t di = (size_t)(bx * 32 + tq + j) * R + by * 32 + tx;
        split_store(v, dh, dl, di);
    }
}

// ---------------- HMMA GEMM, BK=64, SW128, 3-stage cp.async -----------------
// MODE 0: g_xz[8192,2048] = A1 @ W1t^T   (K=512)
// MODE 1: g_yo[8192, 512] = A2 @ W2t^T   (K=1024)
#define STAGE_BYTES 65536
#define GEMM_SMEM   (3 * STAGE_BYTES)
template<int MODE>
__global__ __launch_bounds__(256)
void gemm_hmma() {
    constexpr int N = (MODE == 0) ? 2 * DINNER : DMODEL;
    constexpr int K = (MODE == 0) ? DMODEL : DINNER;
    constexpr int KT = K / 64;
    const __nv_bfloat16* Ah_g = (MODE == 0) ? gA1h : gA2h;
    const __nv_bfloat16* Al_g = (MODE == 0) ? gA1l : gA2l;
    const __nv_bfloat16* Bh_g = (MODE == 0) ? gW1h : gW2h;
    const __nv_bfloat16* Bl_g = (MODE == 0) ? gW1l : gW2l;
    float* C = (MODE == 0) ? g_xz : g_yo;

    extern __shared__ __align__(1024) char smem[];
    const uint32_t oAh = 0, oAl = 16384, oBh = 32768, oBl = 49152;
    uint32_t sb = smem_u32(smem);
    int tid = threadIdx.x, lane = tid & 31, wid = tid >> 5;
    int bx = blockIdx.x, by = blockIdx.y;
    int m0 = (wid >> 1) * 32;
    int n0 = (wid & 1) * 64;

    float c[2][8][4];
    #pragma unroll
    for (int i = 0; i < 2; i++)
        #pragma unroll
        for (int j = 0; j < 8; j++)
            #pragma unroll
            for (int q = 0; q < 4; q++) c[i][j][q] = 0.0f;

    auto issue = [&](int stage, int kt) {
        uint32_t s0 = sb + stage * STAGE_BYTES;
        #pragma unroll
        for (int i = 0; i < 4; i++) {
            int idx = tid + i * 256;
            int row = idx >> 3, c8 = idx & 7;
            size_t ga = (size_t)(by * 128 + row) * K + kt * 64 + c8 * 8;
            size_t gb = (size_t)(bx * 128 + row) * K + kt * 64 + c8 * 8;
            uint32_t off = row * 128 + c8 * 16;
            uint32_t sw = off ^ ((off >> 3) & 0x70);
            cpasync16(s0 + oAh + sw, Ah_g + ga);
            cpasync16(s0 + oAl + sw, Al_g + ga);
            cpasync16(s0 + oBh + sw, Bh_g + gb);
            cpasync16(s0 + oBl + sw, Bl_g + gb);
        }
        cp_commit();
    };

    issue(0, 0);
    if (KT > 1) issue(1, 1);
    int cur = 0;
    for (int kt = 0; kt < KT; kt++) {
        if (kt + 2 < KT)      { issue((cur + 2) % 3, kt + 2); cp_wait2(); }
        else if (kt + 1 < KT) { cp_wait1(); }
        else                  { cp_wait0(); }
        __syncthreads();
        uint32_t bb = sb + cur * STAGE_BYTES;
        #pragma unroll
        for (int ks = 0; ks < 4; ks++) {
            int r = lane & 15, chs = ks * 2 + (lane >> 4);
            uint32_t ah[2][4], al[2][4];
            #pragma unroll
            for (int mi = 0; mi < 2; mi++) {
                uint32_t off = (m0 + mi * 16 + r) * 128 + chs * 16;
                uint32_t sw = off ^ ((off >> 3) & 0x70);
                ldsm4(ah[mi], bb + oAh + sw);
                ldsm4(al[mi], bb + oAl + sw);
            }
            #pragma unroll
            for (int nq = 0; nq < 4; nq++) {
                uint32_t off = (n0 + nq * 16 + r) * 128 + chs * 16;
                uint32_t sw = off ^ ((off >> 3) & 0x70);
                uint32_t bh[4], bl[4];
                ldsm4(bh, bb + oBh + sw);
                ldsm4(bl, bb + oBl + sw);
                #pragma unroll
                for (int mi = 0; mi < 2; mi++) {
                    #pragma unroll
                    for (int sub = 0; sub < 2; sub++) {
                        float* cc = c[mi][nq * 2 + sub];
                        uint32_t b0 = sub ? bh[1] : bh[0];
                        uint32_t b1 = sub ? bh[3] : bh[2];
                        mma16816(cc, ah[mi], b0, b1);
                        mma16816(cc, al[mi], b0, b1);
                        uint32_t l0 = sub ? bl[1] : bl[0];
                        uint32_t l1 = sub ? bl[3] : bl[2];
                        mma16816(cc, ah[mi], l0, l1);
                    }
                }
            }
        }
        __syncthreads();
        cur = (cur + 1) % 3;
    }

    int gid = lane >> 2, tig = lane & 3;
    #pragma unroll
    for (int mi = 0; mi < 2; mi++) {
        #pragma unroll
        for (int nb = 0; nb < 8; nb++) {
            float* p = C + (size_t)(by * 128 + m0 + mi * 16 + gid) * N
                         + bx * 128 + n0 + nb * 8 + 2 * tig;
            float2 v0; v0.x = c[mi][nb][0]; v0.y = c[mi][nb][1];
            float2 v1; v1.x = c[mi][nb][2]; v1.y = c[mi][nb][3];
            *reinterpret_cast<float2*>(p) = v0;
            *reinterpret_cast<float2*>(p + (size_t)8 * N) = v1;
        }
    }
}

// ---------------- causal depthwise conv (width 4) + bias + silu -------------
__global__ void conv_silu_kernel(const float* __restrict__ conv_w,
                                 const float* __restrict__ conv_b) {
    int idx = blockIdx.x * blockDim.x + threadIdx.x;
    int e = idx & (DINNER - 1);
    int row = idx >> 10;
    int l = row & (LSEQ - 1);
    int base = row * 2 * DINNER + e;
    float w0 = conv_w[e * 4 + 0], w1 = conv_w[e * 4 + 1];
    float w2 = conv_w[e * 4 + 2], w3 = conv_w[e * 4 + 3];
    float v = conv_b[e];
    if (l >= 3) v += g_xz[base - 3 * 2 * DINNER] * w0;
    if (l >= 2) v += g_xz[base - 2 * 2 * DINNER] * w1;
    if (l >= 1) v += g_xz[base - 1 * 2 * DINNER] * w2;
    v += g_xz[base] * w3;
    g_u[idx] = v / (1.0f + __expf(-v));
}

// ---------------- x_dbl = u @ W_xproj (8192 x 1024 x 64) --------------------
// 16-row tiles, 256 threads (16 rows x 16 colgroups), FFMA2. grid = 512.
__global__ __launch_bounds__(256)
void xproj_kernel(const float* __restrict__ W) {
    __shared__ float As[32][17];   // [k][row]
    __shared__ float Bs[32][64];
    int tid = threadIdx.x;
    int by = blockIdx.x;
    const float* Ab = g_u + (size_t)(by * 16) * DINNER;
    int ty = tid >> 4, tx = tid & 15;

    unsigned long long acc2[2];
    acc2[0] = 0ull; acc2[1] = 0ull;

    for (int k0 = 0; k0 < DINNER; k0 += 32) {
        if (tid < 128) {
            int row = tid >> 3, c4 = (tid & 7) * 4;
            float4 av = *reinterpret_cast<const float4*>(Ab + (size_t)row * DINNER + k0 + c4);
            As[c4 + 0][row] = av.x;
            As[c4 + 1][row] = av.y;
            As[c4 + 2][row] = av.z;
            As[c4 + 3][row] = av.w;
        } else {
            int t2 = tid - 128;
            #pragma unroll
            for (int j = 0; j < 4; j++) {
                int idx = t2 + j * 128;
                int brow = idx >> 4, bcol = (idx & 15) * 4;
                *reinterpret_cast<float4*>(&Bs[brow][bcol]) =
                    *reinterpret_cast<const float4*>(W + (size_t)(k0 + brow) * XPROJN + bcol);
            }
        }
        __syncthreads();
        #pragma unroll 8
        for (int k = 0; k < 32; k++) {
            unsigned long long a2 = pack2(As[k][ty]);
            ulonglong2 rb = *reinterpret_cast<const ulonglong2*>(&Bs[k][tx * 4]);
            fma2(acc2[0], a2, rb.x);
            fma2(acc2[1], a2, rb.y);
        }
        __syncthreads();
    }
    ulonglong2 v; v.x = acc2[0]; v.y = acc2[1];
    *reinterpret_cast<ulonglong2*>(g_xdbl + (size_t)(by * 16 + ty) * XPROJN + tx * 4) = v;
}

// ---------------- dt = softplus(dt_r @ W_dt + b_dt) -------------------------
__global__ __launch_bounds__(256)
void dtproj_kernel(const float* __restrict__ W_dt, const float* __restrict__ b_dt) {
    __shared__ float dtr_s[8][DTRANK];
    int tid = threadIdx.x;
    int r0 = blockIdx.x * 8;
    {
        int r = tid >> 5, k = tid & 31;
        dtr_s[r][k] = g_xdbl[(size_t)(r0 + r) * XPROJN + k];
    }
    __syncthreads();
    float acc[8][4];
    #pragma unroll
    for (int i = 0; i < 8; i++)
        #pragma unroll
        for (int j = 0; j < 4; j++) acc[i][j] = 0.0f;
    #pragma unroll 4
    for (int k = 0; k < DTRANK; k++) {
        float wv[4];
        #pragma unroll
        for (int j = 0; j < 4; j++) wv[j] = W_dt[(size_t)k * DINNER + tid + j * 256];
        #pragma unroll
        for (int i = 0; i < 8; i++) {
            float a = dtr_s[i][k];
            #pragma unroll
            for (int j = 0; j < 4; j++) acc[i][j] = fmaf(a, wv[j], acc[i][j]);
        }
    }
    #pragma unroll
    for (int j = 0; j < 4; j++) {
        int col = tid + j * 256;
        float bb = b_dt[col];
        #pragma unroll
        for (int i = 0; i < 8; i++) {
            float v = acc[i][j] + bb;
            float sp = (v > 20.0f) ? v : log1pf(__expf(v));
            g_dt[(size_t)(r0 + i) * DINNER + col] = sp;
        }
    }
}

// ---------------- chunked selective scan ------------------------------------
// scan1: per-chunk local scan from h=0 -> S_c, sum(dt).  grid (8, BATCH, NC)
__global__ __launch_bounds__(128)
void scan1_kernel(const float* __restrict__ A_log) {
    __shared__ float dt_s[LC][128];
    __shared__ float u_s [LC][128];
    __shared__ float B_s [LC][DSTATE];
    int tid = threadIdx.x;
    int e = blockIdx.x * 128 + tid;
    int b = blockIdx.y, cch = blockIdx.z;
    int l0 = cch * LC;

    float Ar[DSTATE];
    #pragma unroll
    for (int n = 0; n < DSTATE; n++) Ar[n] = -__expf(A_log[e * DSTATE + n]);

    #pragma unroll
    for (int t = 0; t < LC; t++) {
        size_t row = (size_t)(b * LSEQ + l0 + t);
        dt_s[t][tid] = g_dt[row * DINNER + e];
        u_s [t][tid] = g_u [row * DINNER + e];
    }
    for (int idx = tid; idx < LC * DSTATE; idx += 128) {
        int t = idx >> 4, n = idx & 15;
        size_t row = (size_t)(b * LSEQ + l0 + t);
        B_s[t][n] = g_xdbl[row * XPROJN + DTRANK + n];
    }
    __syncthreads();

    float h[DSTATE];
    #pragma unroll
    for (int n = 0; n < DSTATE; n++) h[n] = 0.0f;
    float dts = 0.0f;
    #pragma unroll 4
    for (int t = 0; t < LC; t++) {
        float dt = dt_s[t][tid];
        dts += dt;
        float du = dt * u_s[t][tid];
        #pragma unroll
        for (int n = 0; n < DSTATE; n++) {
            float dA = __expf(dt * Ar[n]);
            h[n] = fmaf(dA, h[n], du * B_s[t][n]);
        }
    }
    size_t sbase = ((size_t)(cch * BATCH + b) * DINNER + e);
    float* Sp = g_S + sbase * DSTATE;
    #pragma unroll
    for (int n = 0; n < DSTATE; n += 4) {
        float4 v; v.x = h[n]; v.y = h[n + 1]; v.z = h[n + 2]; v.w = h[n + 3];
        *reinterpret_cast<float4*>(Sp + n) = v;
    }
    g_dts[sbase] = dts;
}

// scan2: chunk stitch, parallel over (channel, state). grid (64, BATCH), 256 thr
__global__ __launch_bounds__(256)
void scan2_kernel(const float* __restrict__ A_log) {
    int tid = threadIdx.x;
    int el = tid >> 4, n = tid & 15;
    int e = blockIdx.x * 16 + el;
    int b = blockIdx.y;
    float Ar = -__expf(A_log[e * DSTATE + n]);
    float h = 0.0f;
    #pragma unroll 4
    for (int cch = 0; cch < NC; cch++) {
        size_t sbase = ((size_t)(cch * BATCH + b) * DINNER + e);
        float dts = g_dts[sbase];
        g_Hini[sbase * DSTATE + n] = h;
        h = fmaf(__expf(Ar * dts), h, g_S[sbase * DSTATE + n]);
    }
}

// scan3: replay chunk with true init state, emit gated output. grid (8,BATCH,NC)
__global__ __launch_bounds__(128)
void scan3_kernel(const float* __restrict__ A_log, const float* __restrict__ D_param) {
    __shared__ float dt_s[LC][128];
    __shared__ float u_s [LC][128];
    __shared__ float B_s [LC][DSTATE];
    __shared__ float C_s [LC][DSTATE];
    int tid = threadIdx.x;
    int e = blockIdx.x * 128 + tid;
    int b = blockIdx.y, cch = blockIdx.z;
    int l0 = cch * LC;

    float Ar[DSTATE];
    #pragma unroll
    for (int n = 0; n < DSTATE; n++) Ar[n] = -__expf(A_log[e * DSTATE + n]);
    float Dp = D_param[e];

    #pragma unroll
    for (int t = 0; t < LC; t++) {
        size_t row = (size_t)(b * LSEQ + l0 + t);
        dt_s[t][tid] = g_dt[row * DINNER + e];
        u_s [t][tid] = g_u [row * DINNER + e];
    }
    for (int idx = tid; idx < LC * DSTATE; idx += 128) {
        int t = idx >> 4, n = idx & 15;
        size_t row = (size_t)(b * LSEQ + l0 + t);
        B_s[t][n] = g_xdbl[row * XPROJN + DTRANK + n];
        C_s[t][n] = g_xdbl[row * XPROJN + DTRANK + DSTATE + n];
    }
    __syncthreads();

    float h[DSTATE];
    {
        const float* Hp = g_Hini + ((size_t)(cch * BATCH + b) * DINNER + e) * DSTATE;
        #pragma unroll
        for (int n = 0; n < DSTATE; n += 4) {
            float4 v = *reinterpret_cast<const float4*>(Hp + n);
            h[n] = v.x; h[n + 1] = v.y; h[n + 2] = v.z; h[n + 3] = v.w;
        }
    }

    #pragma unroll 4
    for (int t = 0; t < LC; t++) {
        float dt = dt_s[t][tid];
        float u  = u_s [t][tid];
        float du = dt * u;
        float y = 0.0f;
        #pragma unroll
        for (int n = 0; n < DSTATE; n++) {
            float dA = __expf(dt * Ar[n]);
            h[n] = fmaf(dA, h[n], du * B_s[t][n]);
            y = fmaf(h[n], C_s[t][n], y);
        }
        size_t row = (size_t)(b * LSEQ + l0 + t);
        float z = g_xz[row * 2 * DINNER + DINNER + e];
        float g = z / (1.0f + __expf(-z));
        split_store((y + u * Dp) * g, gA2h, gA2l, row * DINNER + e);
    }
}

// ---------------- launch ----------------------------------------------------
extern "C" void kernel_launch(void* const* d_in, const int* in_sizes, int n_in,
                              void* d_out, int out_size) {
    const float* x      = (const float*)d_in[0];
    const float* ln1_w  = (const float*)d_in[1];
    const float* ln1_b  = (const float*)d_in[2];
    const float* ln2_w  = (const float*)d_in[3];
    const float* ln2_b  = (const float*)d_in[4];
    const float* W_in   = (const float*)d_in[5];
    const float* conv_w = (const float*)d_in[6];
    const float* conv_b = (const float*)d_in[7];
    const float* W_xprj = (const float*)d_in[8];
    const float* W_dt   = (const float*)d_in[9];
    const float* b_dt   = (const float*)d_in[10];
    const float* A_log  = (const float*)d_in[11];
    const float* D_prm  = (const float*)d_in[12];
    const float* W_out  = (const float*)d_in[13];
    float* out = (float*)d_out;

    static int attr_done = 0;
    if (!attr_done) {
        cudaFuncSetAttribute(gemm_hmma<0>, cudaFuncAttributeMaxDynamicSharedMemorySize, GEMM_SMEM);
        cudaFuncSetAttribute(gemm_hmma<1>, cudaFuncAttributeMaxDynamicSharedMemorySize, GEMM_SMEM);
        attr_done = 1;
    }

    // 0) weight transposes + splits (merged)
    tsplit_all<<<1536, 256>>>(W_in, W_out);
    // 1) LN1 -> split bf16 A1
    ln_kernel<0><<<NROWS, 128>>>(x, ln1_w, ln1_b, nullptr);
    // 2) g_xz = A1 @ W_in (HMMA, 3-stage pipeline)
    gemm_hmma<0><<<dim3(2 * DINNER / 128, NROWS / 128), 256, GEMM_SMEM>>>();
    // 3) depthwise causal conv + silu -> g_u
    conv_silu_kernel<<<NROWS * DINNER / 256, 256>>>(conv_w, conv_b);
    // 4) g_xdbl = g_u @ W_xproj
    xproj_kernel<<<NROWS / 16, 256>>>(W_xprj);
    // 5) g_dt = softplus(dt_r @ W_dt + b_dt)
    dtproj_kernel<<<NROWS / 8, 256>>>(W_dt, b_dt);
    // 6) chunked selective scan -> split bf16 A2
    scan1_kernel<<<dim3(DINNER / 128, BATCH, NC), 128>>>(A_log);
    scan2_kernel<<<dim3(DINNER / 16, BATCH), 256>>>(A_log);
    scan3_kernel<<<dim3(DINNER / 128, BATCH, NC), 128>>>(A_log, D_prm);
    // 7) g_yo = A2 @ W_out (HMMA, 3-stage pipeline)
    gemm_hmma<1><<<dim3(DMODEL / 128, NROWS / 128), 256, GEMM_SMEM>>>();
    // 8) out = LN2(x + g_yo)
    ln_kernel<1><<<NROWS, 128>>>(x, ln2_w, ln2_b, out);
}

// round 13
// speedup vs baseline: 1.1689x; 1.1163x over previous
#include <cuda_runtime.h>
#include <cuda_bf16.h>
#include <math.h>
#include <stdint.h>

#define BATCH   4
#define LSEQ    2048
#define DMODEL  512
#define DINNER  1024
#define DSTATE  16
#define DTRANK  32
#define NROWS   (BATCH * LSEQ)         // 8192
#define XPROJN  (DTRANK + 2 * DSTATE)  // 64
#define NC      64                     // scan chunks
#define LC      32                     // steps per chunk

// ---------------- scratch (static device globals: no allocs allowed) --------
__device__ float g_xz  [NROWS * 2 * DINNER];    // [u_raw | z]
__device__ float g_u   [NROWS * DINNER];        // silu(conv(u)+b)
__device__ float g_xdbl[NROWS * XPROJN];        // [dt_r | B | C]
__device__ float g_dt  [NROWS * DINNER];        // softplus(dt)
__device__ float g_yo  [NROWS * DMODEL];        // y @ W_out
__device__ float g_S    [NC * BATCH * DINNER * DSTATE];  // chunk end states
__device__ float g_Hini [NC * BATCH * DINNER * DSTATE];  // chunk init states
__device__ float g_dts  [NC * BATCH * DINNER];           // chunk dt sums

// bf16 split operands for tensor-core GEMMs
__device__ __nv_bfloat16 gA1h[NROWS * DMODEL],  gA1l[NROWS * DMODEL];   // LN1 out
__device__ __nv_bfloat16 gA2h[NROWS * DINNER],  gA2l[NROWS * DINNER];   // scan out
__device__ __nv_bfloat16 gW1h[2 * DINNER * DMODEL], gW1l[2 * DINNER * DMODEL]; // W_in^T  [2048][512]
__device__ __nv_bfloat16 gW2h[DMODEL * DINNER],     gW2l[DMODEL * DINNER];     // W_out^T [512][1024]

// ---------------- helpers ----------------------------------------------------
__device__ __forceinline__ uint32_t smem_u32(const void* p) {
    uint32_t a;
    asm("{ .reg .u64 t; cvta.to.shared.u64 t, %1; cvt.u32.u64 %0, t; }" : "=r"(a) : "l"(p));
    return a;
}
__device__ __forceinline__ void split_store(float v, __nv_bfloat16* h, __nv_bfloat16* l, size_t i) {
    __nv_bfloat16 hb = __float2bfloat16(v);
    h[i] = hb;
    l[i] = __float2bfloat16(v - __bfloat162float(hb));
}
__device__ __forceinline__ void ldsm4(uint32_t* r, uint32_t addr) {
    asm volatile("ldmatrix.sync.aligned.m8n8.x4.shared.b16 {%0,%1,%2,%3}, [%4];"
                 : "=r"(r[0]), "=r"(r[1]), "=r"(r[2]), "=r"(r[3]) : "r"(addr));
}
__device__ __forceinline__ void mma16816(float* c, const uint32_t* a, uint32_t b0, uint32_t b1) {
    asm volatile(
        "mma.sync.aligned.m16n8k16.row.col.f32.bf16.bf16.f32 "
        "{%0,%1,%2,%3}, {%4,%5,%6,%7}, {%8,%9}, {%0,%1,%2,%3};"
        : "+f"(c[0]), "+f"(c[1]), "+f"(c[2]), "+f"(c[3])
        : "r"(a[0]), "r"(a[1]), "r"(a[2]), "r"(a[3]), "r"(b0), "r"(b1));
}
__device__ __forceinline__ void cpasync16(uint32_t dst, const void* src) {
    asm volatile("cp.async.cg.shared.global [%0], [%1], 16;" :: "r"(dst), "l"(src));
}
__device__ __forceinline__ void cp_commit() { asm volatile("cp.async.commit_group;" ::: "memory"); }
__device__ __forceinline__ void cp_wait1()  { asm volatile("cp.async.wait_group 1;" ::: "memory"); }
__device__ __forceinline__ void cp_wait0()  { asm volatile("cp.async.wait_group 0;" ::: "memory"); }
// packed fp32x2 (xproj)
__device__ __forceinline__ unsigned long long pack2(float a) {
    unsigned long long r;
    asm("mov.b64 %0, {%1, %1};" : "=l"(r) : "f"(a));
    return r;
}
__device__ __forceinline__ void fma2(unsigned long long& d,
                                     unsigned long long a,
                                     unsigned long long b) {
    asm("fma.rn.f32x2 %0, %1, %2, %0;" : "+l"(d) : "l"(a), "l"(b));
}

// ---------------- layernorm ---------------------------------------------------
template<int MODE>
__global__ void ln_kernel(const float* __restrict__ x,
                          const float* __restrict__ w,
                          const float* __restrict__ b,
                          float* __restrict__ outp) {
    __shared__ float sbuf[4];
    int row = blockIdx.x;
    int tid = threadIdx.x;
    float4 v = reinterpret_cast<const float4*>(x + (size_t)row * DMODEL)[tid];
    if (MODE == 1) {
        float4 r = reinterpret_cast<const float4*>(g_yo + (size_t)row * DMODEL)[tid];
        v.x += r.x; v.y += r.y; v.z += r.z; v.w += r.w;
    }
    float s = v.x + v.y + v.z + v.w;
    #pragma unroll
    for (int o = 16; o > 0; o >>= 1) s += __shfl_xor_sync(0xffffffffu, s, o);
    if ((tid & 31) == 0) sbuf[tid >> 5] = s;
    __syncthreads();
    float mean = (sbuf[0] + sbuf[1] + sbuf[2] + sbuf[3]) * (1.0f / DMODEL);
    __syncthreads();
    float dx = v.x - mean, dy = v.y - mean, dz = v.z - mean, dw = v.w - mean;
    float sq = dx * dx + dy * dy + dz * dz + dw * dw;
    #pragma unroll
    for (int o = 16; o > 0; o >>= 1) sq += __shfl_xor_sync(0xffffffffu, sq, o);
    if ((tid & 31) == 0) sbuf[tid >> 5] = sq;
    __syncthreads();
    float var = (sbuf[0] + sbuf[1] + sbuf[2] + sbuf[3]) * (1.0f / DMODEL);
    float inv = rsqrtf(var + 1e-5f);
    float4 wv = reinterpret_cast<const float4*>(w)[tid];
    float4 bv = reinterpret_cast<const float4*>(b)[tid];
    float o0 = dx * inv * wv.x + bv.x;
    float o1 = dy * inv * wv.y + bv.y;
    float o2 = dz * inv * wv.z + bv.z;
    float o3 = dw * inv * wv.w + bv.w;
    if (MODE == 0) {
        size_t base = (size_t)row * DMODEL + tid * 4;
        split_store(o0, gA1h, gA1l, base + 0);
        split_store(o1, gA1h, gA1l, base + 1);
        split_store(o2, gA1h, gA1l, base + 2);
        split_store(o3, gA1h, gA1l, base + 3);
    } else {
        float4 o4; o4.x = o0; o4.y = o1; o4.z = o2; o4.w = o3;
        reinterpret_cast<float4*>(outp + (size_t)row * DMODEL)[tid] = o4;
    }
}

// ---------------- transpose + bf16 split for both weights (merged) ----------
__global__ void tsplit_all(const float* __restrict__ W_in,
                           const float* __restrict__ W_out) {
    int blk = blockIdx.x;
    int R, Cc, bx, by;
    const float* src;
    __nv_bfloat16 *dh, *dl;
    if (blk < 1024) {               // W_in [512][2048] -> [2048][512]
        R = DMODEL; Cc = 2 * DINNER; src = W_in; dh = gW1h; dl = gW1l;
        bx = blk & 63; by = blk >> 6;
    } else {                        // W_out [1024][512] -> [512][1024]
        int b2 = blk - 1024;
        R = DINNER; Cc = DMODEL; src = W_out; dh = gW2h; dl = gW2l;
        bx = b2 & 15; by = b2 >> 4;
    }
    __shared__ float t[32][33];
    int tx = threadIdx.x & 31, tq = threadIdx.x >> 5;
    #pragma unroll
    for (int j = 0; j < 32; j += 8)
        t[tq + j][tx] = src[(size_t)(by * 32 + tq + j) * Cc + bx * 32 + tx];
    __syncthreads();
    #pragma unroll
    for (int j = 0; j < 32; j += 8) {
        float v = t[tx][tq + j];
        size_t di = (size_t)(bx * 32 + tq + j) * R + by * 32 + tx;
        split_store(v, dh, dl, di);
    }
}

// ---------------- HMMA GEMM, BK=64, SW128, 2-stage cp.async (R7 proven) -----
// MODE 0: g_xz[8192,2048] = A1 @ W1t^T   (K=512)
// MODE 1: g_yo[8192, 512] = A2 @ W2t^T   (K=1024)
#define STAGE_BYTES 65536
#define GEMM_SMEM   (2 * STAGE_BYTES)
template<int MODE>
__global__ __launch_bounds__(256)
void gemm_hmma() {
    constexpr int N = (MODE == 0) ? 2 * DINNER : DMODEL;
    constexpr int K = (MODE == 0) ? DMODEL : DINNER;
    constexpr int KT = K / 64;
    const __nv_bfloat16* Ah_g = (MODE == 0) ? gA1h : gA2h;
    const __nv_bfloat16* Al_g = (MODE == 0) ? gA1l : gA2l;
    const __nv_bfloat16* Bh_g = (MODE == 0) ? gW1h : gW2h;
    const __nv_bfloat16* Bl_g = (MODE == 0) ? gW1l : gW2l;
    float* C = (MODE == 0) ? g_xz : g_yo;

    extern __shared__ __align__(1024) char smem[];
    const uint32_t oAh = 0, oAl = 16384, oBh = 32768, oBl = 49152;
    uint32_t sb = smem_u32(smem);
    int tid = threadIdx.x, lane = tid & 31, wid = tid >> 5;
    int bx = blockIdx.x, by = blockIdx.y;
    int m0 = (wid >> 1) * 32;
    int n0 = (wid & 1) * 64;

    float c[2][8][4];
    #pragma unroll
    for (int i = 0; i < 2; i++)
        #pragma unroll
        for (int j = 0; j < 8; j++)
            #pragma unroll
            for (int q = 0; q < 4; q++) c[i][j][q] = 0.0f;

    auto issue = [&](int stage, int kt) {
        uint32_t s0 = sb + stage * STAGE_BYTES;
        #pragma unroll
        for (int i = 0; i < 4; i++) {
            int idx = tid + i * 256;
            int row = idx >> 3, c8 = idx & 7;
            size_t ga = (size_t)(by * 128 + row) * K + kt * 64 + c8 * 8;
            size_t gb = (size_t)(bx * 128 + row) * K + kt * 64 + c8 * 8;
            uint32_t off = row * 128 + c8 * 16;
            uint32_t sw = off ^ ((off >> 3) & 0x70);
            cpasync16(s0 + oAh + sw, Ah_g + ga);
            cpasync16(s0 + oAl + sw, Al_g + ga);
            cpasync16(s0 + oBh + sw, Bh_g + gb);
            cpasync16(s0 + oBl + sw, Bl_g + gb);
        }
        cp_commit();
    };

    issue(0, 0);
    for (int kt = 0; kt < KT; kt++) {
        int cur = kt & 1;
        if (kt + 1 < KT) { issue(cur ^ 1, kt + 1); cp_wait1(); }
        else             { cp_wait0(); }
        __syncthreads();
        uint32_t bb = sb + cur * STAGE_BYTES;
        #pragma unroll
        for (int ks = 0; ks < 4; ks++) {
            int r = lane & 15, chs = ks * 2 + (lane >> 4);
            uint32_t ah[2][4], al[2][4];
            #pragma unroll
            for (int mi = 0; mi < 2; mi++) {
                uint32_t off = (m0 + mi * 16 + r) * 128 + chs * 16;
                uint32_t sw = off ^ ((off >> 3) & 0x70);
                ldsm4(ah[mi], bb + oAh + sw);
                ldsm4(al[mi], bb + oAl + sw);
            }
            #pragma unroll
            for (int nq = 0; nq < 4; nq++) {
                uint32_t off = (n0 + nq * 16 + r) * 128 + chs * 16;
                uint32_t sw = off ^ ((off >> 3) & 0x70);
                uint32_t bh[4], bl[4];
                ldsm4(bh, bb + oBh + sw);
                ldsm4(bl, bb + oBl + sw);
                #pragma unroll
                for (int mi = 0; mi < 2; mi++) {
                    #pragma unroll
                    for (int sub = 0; sub < 2; sub++) {
                        float* cc = c[mi][nq * 2 + sub];
                        uint32_t b0 = sub ? bh[1] : bh[0];
                        uint32_t b1 = sub ? bh[3] : bh[2];
                        mma16816(cc, ah[mi], b0, b1);
                        mma16816(cc, al[mi], b0, b1);
                        uint32_t l0 = sub ? bl[1] : bl[0];
                        uint32_t l1 = sub ? bl[3] : bl[2];
                        mma16816(cc, ah[mi], l0, l1);
                    }
                }
            }
        }
        __syncthreads();
    }

    int gid = lane >> 2, tig = lane & 3;
    #pragma unroll
    for (int mi = 0; mi < 2; mi++) {
        #pragma unroll
        for (int nb = 0; nb < 8; nb++) {
            float* p = C + (size_t)(by * 128 + m0 + mi * 16 + gid) * N
                         + bx * 128 + n0 + nb * 8 + 2 * tig;
            float2 v0; v0.x = c[mi][nb][0]; v0.y = c[mi][nb][1];
            float2 v1; v1.x = c[mi][nb][2]; v1.y = c[mi][nb][3];
            *reinterpret_cast<float2*>(p) = v0;
            *reinterpret_cast<float2*>(p + (size_t)8 * N) = v1;
        }
    }
}

// ---------------- causal depthwise conv (width 4) + bias + silu -------------
__global__ void conv_silu_kernel(const float* __restrict__ conv_w,
                                 const float* __restrict__ conv_b) {
    int idx = blockIdx.x * blockDim.x + threadIdx.x;
    int e = idx & (DINNER - 1);
    int row = idx >> 10;
    int l = row & (LSEQ - 1);
    int base = row * 2 * DINNER + e;
    float w0 = conv_w[e * 4 + 0], w1 = conv_w[e * 4 + 1];
    float w2 = conv_w[e * 4 + 2], w3 = conv_w[e * 4 + 3];
    float v = conv_b[e];
    if (l >= 3) v += g_xz[base - 3 * 2 * DINNER] * w0;
    if (l >= 2) v += g_xz[base - 2 * 2 * DINNER] * w1;
    if (l >= 1) v += g_xz[base - 1 * 2 * DINNER] * w2;
    v += g_xz[base] * w3;
    g_u[idx] = v / (1.0f + __expf(-v));
}

// ---------------- x_dbl = u @ W_xproj (8192 x 1024 x 64) --------------------
// 32x64 tile, BK=32, 128 threads, 4x4 micro-tile, FFMA2 (R7 proven). grid=256
__global__ __launch_bounds__(128)
void xproj_kernel(const float* __restrict__ W) {
    __shared__ float As[32][36];
    __shared__ float Bs[32][64];
    int tid = threadIdx.x;
    int by = blockIdx.x;
    const float* Ab = g_u + (size_t)(by * 32) * DINNER;

    int arow = tid >> 2, acol = (tid & 3) * 4;
    int brow = tid >> 4, bcol = (tid & 15) * 4;
    int tx = tid & 15, ty = tid >> 4;

    unsigned long long acc2[4][2];
    #pragma unroll
    for (int i = 0; i < 4; i++) { acc2[i][0] = 0ull; acc2[i][1] = 0ull; }

    for (int k0 = 0; k0 < DINNER; k0 += 32) {
        #pragma unroll
        for (int half = 0; half < 2; half++) {
            int cc = acol + half * 16;
            float4 av = *reinterpret_cast<const float4*>(Ab + (size_t)arow * DINNER + k0 + cc);
            As[cc + 0][arow] = av.x;
            As[cc + 1][arow] = av.y;
            As[cc + 2][arow] = av.z;
            As[cc + 3][arow] = av.w;
        }
        #pragma unroll
        for (int q = 0; q < 4; q++) {
            int r = brow + q * 8;
            float4 bv = *reinterpret_cast<const float4*>(W + (size_t)(k0 + r) * XPROJN + bcol);
            *reinterpret_cast<float4*>(&Bs[r][bcol]) = bv;
        }
        __syncthreads();
        #pragma unroll 8
        for (int k = 0; k < 32; k++) {
            float4 ra = *reinterpret_cast<const float4*>(&As[k][ty * 4]);
            ulonglong2 rb = *reinterpret_cast<const ulonglong2*>(&Bs[k][tx * 4]);
            unsigned long long ap[4];
            ap[0] = pack2(ra.x); ap[1] = pack2(ra.y);
            ap[2] = pack2(ra.z); ap[3] = pack2(ra.w);
            #pragma unroll
            for (int i = 0; i < 4; i++) {
                fma2(acc2[i][0], ap[i], rb.x);
                fma2(acc2[i][1], ap[i], rb.y);
            }
        }
        __syncthreads();
    }
    float* Cb = g_xdbl + (size_t)(by * 32 + ty * 4) * XPROJN + tx * 4;
    #pragma unroll
    for (int i = 0; i < 4; i++) {
        ulonglong2 v; v.x = acc2[i][0]; v.y = acc2[i][1];
        *reinterpret_cast<ulonglong2*>(Cb + (size_t)i * XPROJN) = v;
    }
}

// ---------------- dt = softplus(dt_r @ W_dt + b_dt) -------------------------
__global__ __launch_bounds__(256)
void dtproj_kernel(const float* __restrict__ W_dt, const float* __restrict__ b_dt) {
    __shared__ float dtr_s[8][DTRANK];
    int tid = threadIdx.x;
    int r0 = blockIdx.x * 8;
    {
        int r = tid >> 5, k = tid & 31;
        dtr_s[r][k] = g_xdbl[(size_t)(r0 + r) * XPROJN + k];
    }
    __syncthreads();
    float acc[8][4];
    #pragma unroll
    for (int i = 0; i < 8; i++)
        #pragma unroll
        for (int j = 0; j < 4; j++) acc[i][j] = 0.0f;
    #pragma unroll 4
    for (int k = 0; k < DTRANK; k++) {
        float wv[4];
        #pragma unroll
        for (int j = 0; j < 4; j++) wv[j] = W_dt[(size_t)k * DINNER + tid + j * 256];
        #pragma unroll
        for (int i = 0; i < 8; i++) {
            float a = dtr_s[i][k];
            #pragma unroll
            for (int j = 0; j < 4; j++) acc[i][j] = fmaf(a, wv[j], acc[i][j]);
        }
    }
    #pragma unroll
    for (int j = 0; j < 4; j++) {
        int col = tid + j * 256;
        float bb = b_dt[col];
        #pragma unroll
        for (int i = 0; i < 8; i++) {
            float v = acc[i][j] + bb;
            float sp = (v > 20.0f) ? v : log1pf(__expf(v));
            g_dt[(size_t)(r0 + i) * DINNER + col] = sp;
        }
    }
}

// ---------------- chunked selective scan ------------------------------------
// scan1: per-chunk local scan from h=0 -> S_c, sum(dt).  grid (8, BATCH, NC)
__global__ __launch_bounds__(128)
void scan1_kernel(const float* __restrict__ A_log) {
    __shared__ float dt_s[LC][128];
    __shared__ float u_s [LC][128];
    __shared__ float B_s [LC][DSTATE];
    int tid = threadIdx.x;
    int e = blockIdx.x * 128 + tid;
    int b = blockIdx.y, cch = blockIdx.z;
    int l0 = cch * LC;

    float Ar[DSTATE];
    #pragma unroll
    for (int n = 0; n < DSTATE; n++) Ar[n] = -__expf(A_log[e * DSTATE + n]);

    #pragma unroll
    for (int t = 0; t < LC; t++) {
        size_t row = (size_t)(b * LSEQ + l0 + t);
        dt_s[t][tid] = g_dt[row * DINNER + e];
        u_s [t][tid] = g_u [row * DINNER + e];
    }
    for (int idx = tid; idx < LC * DSTATE; idx += 128) {
        int t = idx >> 4, n = idx & 15;
        size_t row = (size_t)(b * LSEQ + l0 + t);
        B_s[t][n] = g_xdbl[row * XPROJN + DTRANK + n];
    }
    __syncthreads();

    float h[DSTATE];
    #pragma unroll
    for (int n = 0; n < DSTATE; n++) h[n] = 0.0f;
    float dts = 0.0f;
    #pragma unroll 4
    for (int t = 0; t < LC; t++) {
        float dt = dt_s[t][tid];
        dts += dt;
        float du = dt * u_s[t][tid];
        #pragma unroll
        for (int n = 0; n < DSTATE; n++) {
            float dA = __expf(dt * Ar[n]);
            h[n] = fmaf(dA, h[n], du * B_s[t][n]);
        }
    }
    size_t sbase = ((size_t)(cch * BATCH + b) * DINNER + e);
    float* Sp = g_S + sbase * DSTATE;
    #pragma unroll
    for (int n = 0; n < DSTATE; n += 4) {
        float4 v; v.x = h[n]; v.y = h[n + 1]; v.z = h[n + 2]; v.w = h[n + 3];
        *reinterpret_cast<float4*>(Sp + n) = v;
    }
    g_dts[sbase] = dts;
}

// scan2: chunk stitch, parallel over (channel, state). grid (64, BATCH), 256 thr
__global__ __launch_bounds__(256)
void scan2_kernel(const float* __restrict__ A_log) {
    int tid = threadIdx.x;
    int el = tid >> 4, n = tid & 15;
    int e = blockIdx.x * 16 + el;
    int b = blockIdx.y;
    float Ar = -__expf(A_log[e * DSTATE + n]);
    float h = 0.0f;
    #pragma unroll 4
    for (int cch = 0; cch < NC; cch++) {
        size_t sbase = ((size_t)(cch * BATCH + b) * DINNER + e);
        float dts = g_dts[sbase];
        g_Hini[sbase * DSTATE + n] = h;
        h = fmaf(__expf(Ar * dts), h, g_S[sbase * DSTATE + n]);
    }
}

// scan3: replay chunk with true init state, emit gated output. grid (8,BATCH,NC)
__global__ __launch_bounds__(128)
void scan3_kernel(const float* __restrict__ A_log, const float* __restrict__ D_param) {
    __shared__ float dt_s[LC][128];
    __shared__ float u_s [LC][128];
    __shared__ float B_s [LC][DSTATE];
    __shared__ float C_s [LC][DSTATE];
    int tid = threadIdx.x;
    int e = blockIdx.x * 128 + tid;
    int b = blockIdx.y, cch = blockIdx.z;
    int l0 = cch * LC;

    float Ar[DSTATE];
    #pragma unroll
    for (int n = 0; n < DSTATE; n++) Ar[n] = -__expf(A_log[e * DSTATE + n]);
    float Dp = D_param[e];

    #pragma unroll
    for (int t = 0; t < LC; t++) {
        size_t row = (size_t)(b * LSEQ + l0 + t);
        dt_s[t][tid] = g_dt[row * DINNER + e];
        u_s [t][tid] = g_u [row * DINNER + e];
    }
    for (int idx = tid; idx < LC * DSTATE; idx += 128) {
        int t = idx >> 4, n = idx & 15;
        size_t row = (size_t)(b * LSEQ + l0 + t);
        B_s[t][n] = g_xdbl[row * XPROJN + DTRANK + n];
        C_s[t][n] = g_xdbl[row * XPROJN + DTRANK + DSTATE + n];
    }
    __syncthreads();

    float h[DSTATE];
    {
        const float* Hp = g_Hini + ((size_t)(cch * BATCH + b) * DINNER + e) * DSTATE;
        #pragma unroll
        for (int n = 0; n < DSTATE; n += 4) {
            float4 v = *reinterpret_cast<const float4*>(Hp + n);
            h[n] = v.x; h[n + 1] = v.y; h[n + 2] = v.z; h[n + 3] = v.w;
        }
    }

    #pragma unroll 4
    for (int t = 0; t < LC; t++) {
        float dt = dt_s[t][tid];
        float u  = u_s [t][tid];
        float du = dt * u;
        float y = 0.0f;
        #pragma unroll
        for (int n = 0; n < DSTATE; n++) {
            float dA = __expf(dt * Ar[n]);
            h[n] = fmaf(dA, h[n], du * B_s[t][n]);
            y = fmaf(h[n], C_s[t][n], y);
        }
        size_t row = (size_t)(b * LSEQ + l0 + t);
        float z = g_xz[row * 2 * DINNER + DINNER + e];
        float g = z / (1.0f + __expf(-z));
        split_store((y + u * Dp) * g, gA2h, gA2l, row * DINNER + e);
    }
}

// ---------------- launch ----------------------------------------------------
extern "C" void kernel_launch(void* const* d_in, const int* in_sizes, int n_in,
                              void* d_out, int out_size) {
    const float* x      = (const float*)d_in[0];
    const float* ln1_w  = (const float*)d_in[1];
    const float* ln1_b  = (const float*)d_in[2];
    const float* ln2_w  = (const float*)d_in[3];
    const float* ln2_b  = (const float*)d_in[4];
    const float* W_in   = (const float*)d_in[5];
    const float* conv_w = (const float*)d_in[6];
    const float* conv_b = (const float*)d_in[7];
    const float* W_xprj = (const float*)d_in[8];
    const float* W_dt   = (const float*)d_in[9];
    const float* b_dt   = (const float*)d_in[10];
    const float* A_log  = (const float*)d_in[11];
    const float* D_prm  = (const float*)d_in[12];
    const float* W_out  = (const float*)d_in[13];
    float* out = (float*)d_out;

    static int attr_done = 0;
    if (!attr_done) {
        cudaFuncSetAttribute(gemm_hmma<0>, cudaFuncAttributeMaxDynamicSharedMemorySize, GEMM_SMEM);
        cudaFuncSetAttribute(gemm_hmma<1>, cudaFuncAttributeMaxDynamicSharedMemorySize, GEMM_SMEM);
        attr_done = 1;
    }

    // 0) weight transposes + splits (merged)
    tsplit_all<<<1536, 256>>>(W_in, W_out);
    // 1) LN1 -> split bf16 A1
    ln_kernel<0><<<NROWS, 128>>>(x, ln1_w, ln1_b, nullptr);
    // 2) g_xz = A1 @ W_in (HMMA, 2-stage pipeline — R7 proven)
    gemm_hmma<0><<<dim3(2 * DINNER / 128, NROWS / 128), 256, GEMM_SMEM>>>();
    // 3) depthwise causal conv + silu -> g_u
    conv_silu_kernel<<<NROWS * DINNER / 256, 256>>>(conv_w, conv_b);
    // 4) g_xdbl = g_u @ W_xproj (R7 proven 32-row version)
    xproj_kernel<<<NROWS / 32, 128>>>(W_xprj);
    // 5) g_dt = softplus(dt_r @ W_dt + b_dt)
    dtproj_kernel<<<NROWS / 8, 256>>>(W_dt, b_dt);
    // 6) chunked selective scan -> split bf16 A2
    scan1_kernel<<<dim3(DINNER / 128, BATCH, NC), 128>>>(A_log);
    scan2_kernel<<<dim3(DINNER / 16, BATCH), 256>>>(A_log);
    scan3_kernel<<<dim3(DINNER / 128, BATCH, NC), 128>>>(A_log, D_prm);
    // 7) g_yo = A2 @ W_out (HMMA, 2-stage pipeline)
    gemm_hmma<1><<<dim3(DMODEL / 128, NROWS / 128), 256, GEMM_SMEM>>>();
    // 8) out = LN2(x + g_yo)
    ln_kernel<1><<<NROWS, 128>>>(x, ln2_w, ln2_b, out);
}